// round 2
// baseline (speedup 1.0000x reference)
#include <cuda_runtime.h>

#define S_PER_BLK 4
#define T_STEPS   1024
#define H_DIM     64
#define G_DIM     256   // 4*H
#define D_DIM     4
#define NTHREADS  512   // 2 threads per gate row (split-K over H)

typedef unsigned long long ull;

// ---- fast activations (err ~1e-6, well under 1e-3 budget) ----
__device__ __forceinline__ float fsig(float x) {
    float e = __expf(-x);
    float d = 1.0f + e;
    float r;
    asm("rcp.approx.f32 %0, %1;" : "=f"(r) : "f"(d));
    return r;
}
__device__ __forceinline__ float ftanh(float x) {
    return __fmaf_rn(2.0f, fsig(2.0f * x), -1.0f);
}

// ---- packed f32x2 fma (sm_100+) ----
__device__ __forceinline__ void fma2(ull& d, ull a, ull b, ull c) {
    asm("fma.rn.f32x2 %0, %1, %2, %3;" : "=l"(d) : "l"(a), "l"(b), "l"(c));
}
__device__ __forceinline__ float fold2(ull a) {
    float lo, hi;
    asm("mov.b64 {%0,%1}, %2;" : "=f"(lo), "=f"(hi) : "l"(a));
    return lo + hi;
}
__device__ __forceinline__ ull f4lo(const float4& v) {
    ull r; asm("mov.b64 %0, {%1,%2};" : "=l"(r) : "f"(v.x), "f"(v.y)); return r;
}
__device__ __forceinline__ ull f4hi(const float4& v) {
    ull r; asm("mov.b64 %0, {%1,%2};" : "=l"(r) : "f"(v.z), "f"(v.w)); return r;
}

// Dynamic smem layout (floats):
//   xs  : S*T*D  = 16384
//   h1s : S*H    = 256
//   h2s : S*H    = 256
//   ga0 : S*G    = 1024
//   ga1 : S*G    = 1024
//   c1s : S*H    = 256
//   c2s : S*H    = 256
// total = 19456 floats = 77824 bytes

__global__ __launch_bounds__(NTHREADS, 1)
void lstm_fused_kernel(const float* __restrict__ x,
                       const float* __restrict__ W_ih0,
                       const float* __restrict__ W_hh0,
                       const float* __restrict__ b0,
                       const float* __restrict__ W_ih1,
                       const float* __restrict__ W_hh1,
                       const float* __restrict__ b1,
                       const float* __restrict__ W_fc1,
                       const float* __restrict__ b_fc1,
                       const float* __restrict__ W_fc2,
                       const float* __restrict__ b_fc2,
                       float* __restrict__ out)
{
    extern __shared__ float sm[];
    float* xs  = sm;                                   // [S][T][D]
    float* h1s = sm + S_PER_BLK * T_STEPS * D_DIM;     // [S][H]
    float* h2s = h1s + S_PER_BLK * H_DIM;              // [S][H]
    float* ga0 = h2s + S_PER_BLK * H_DIM;              // [S][G]
    float* ga1 = ga0 + S_PER_BLK * G_DIM;              // [S][G]
    float* c1s = ga1 + S_PER_BLK * G_DIM;              // [S][H]
    float* c2s = c1s + S_PER_BLK * H_DIM;              // [S][H]

    const int tid  = threadIdx.x;
    const int g    = tid >> 1;          // gate row 0..255
    const int half = tid & 1;           // K-half: 0 -> h[0:32), 1 -> h[32:64)
    const int bb   = blockIdx.x * S_PER_BLK;

    // ---- this thread's half-rows of the three recurrent matrices (96 regs) ----
    float4 w0[8], w1[8], w2[8];
    {
        const float4* p0 = (const float4*)(W_hh0 + g * H_DIM + half * 32);
        const float4* p1 = (const float4*)(W_ih1 + g * H_DIM + half * 32);
        const float4* p2 = (const float4*)(W_hh1 + g * H_DIM + half * 32);
        #pragma unroll
        for (int i = 0; i < 8; i++) { w0[i] = p0[i]; w1[i] = p1[i]; w2[i] = p2[i]; }
    }
    float wi0[D_DIM];
    #pragma unroll
    for (int d = 0; d < D_DIM; d++) wi0[d] = W_ih0[g * D_DIM + d];
    const float bias0 = b0[g];
    const float bias1 = b1[g];

    // ---- stage x into smem (coalesced, one time) ----
    {
        const float4* gx = (const float4*)(x + (size_t)bb * T_STEPS * D_DIM);
        float4*       sx = (float4*)xs;
        #pragma unroll 4
        for (int i = tid; i < S_PER_BLK * T_STEPS; i += NTHREADS) sx[i] = gx[i];
    }
    for (int i = tid; i < S_PER_BLK * H_DIM; i += NTHREADS) {
        h1s[i] = 0.f; h2s[i] = 0.f; c1s[i] = 0.f; c2s[i] = 0.f;
    }
    __syncthreads();

    const bool is_tanh = (g >= 2 * H_DIM) && (g < 3 * H_DIM);
    const int sA = half * 2;        // this lane activates/writes samples sA, sA+1
    const int sB = half * 2 + 1;

    for (int t = 0; t < T_STEPS; t++) {
        // ---------- layer 0 gate pre-activations (split-K) ----------
        {
            ull acc[S_PER_BLK];
            #pragma unroll
            for (int s = 0; s < S_PER_BLK; s++) acc[s] = 0ULL;
            #pragma unroll
            for (int k = 0; k < 8; k++) {
                #pragma unroll
                for (int s = 0; s < S_PER_BLK; s++) {
                    float4 hv = ((const float4*)(h1s + s * H_DIM + half * 32))[k];
                    fma2(acc[s], f4lo(w0[k]), f4lo(hv), acc[s]);
                    fma2(acc[s], f4hi(w0[k]), f4hi(hv), acc[s]);
                }
            }
            float tot[S_PER_BLK];
            #pragma unroll
            for (int s = 0; s < S_PER_BLK; s++) {
                tot[s] = fold2(acc[s]);
                tot[s] += __shfl_xor_sync(0xffffffffu, tot[s], 1);
            }
            // each lane finalizes its 2 assigned samples (bias + x-part + activation)
            #pragma unroll
            for (int u = 0; u < 2; u++) {
                int s = (u == 0) ? sA : sB;
                float4 xv = ((const float4*)xs)[s * T_STEPS + t];
                float pre = tot[s] + bias0;
                pre = __fmaf_rn(xv.x, wi0[0], pre);
                pre = __fmaf_rn(xv.y, wi0[1], pre);
                pre = __fmaf_rn(xv.z, wi0[2], pre);
                pre = __fmaf_rn(xv.w, wi0[3], pre);
                ga0[s * G_DIM + g] = is_tanh ? ftanh(pre) : fsig(pre);
            }
        }
        __syncthreads();  // B1

        // ---------- layer 0 state update: 256 threads, one (s,h) each ----------
        if (tid < S_PER_BLK * H_DIM) {
            int s = tid >> 6, hh = tid & 63;
            float iv = ga0[s * G_DIM + hh];
            float fv = ga0[s * G_DIM + hh + H_DIM];
            float gv = ga0[s * G_DIM + hh + 2 * H_DIM];
            float ov = ga0[s * G_DIM + hh + 3 * H_DIM];
            float c  = __fmaf_rn(fv, c1s[tid], iv * gv);
            c1s[tid] = c;
            h1s[tid] = ov * ftanh(c);
        }
        __syncthreads();  // B2

        // ---------- layer 1 gate pre-activations (split-K) ----------
        {
            ull acc[S_PER_BLK];
            #pragma unroll
            for (int s = 0; s < S_PER_BLK; s++) acc[s] = 0ULL;
            #pragma unroll
            for (int k = 0; k < 8; k++) {
                #pragma unroll
                for (int s = 0; s < S_PER_BLK; s++) {
                    float4 hv = ((const float4*)(h1s + s * H_DIM + half * 32))[k];
                    fma2(acc[s], f4lo(w1[k]), f4lo(hv), acc[s]);
                    fma2(acc[s], f4hi(w1[k]), f4hi(hv), acc[s]);
                }
            }
            #pragma unroll
            for (int k = 0; k < 8; k++) {
                #pragma unroll
                for (int s = 0; s < S_PER_BLK; s++) {
                    float4 hv = ((const float4*)(h2s + s * H_DIM + half * 32))[k];
                    fma2(acc[s], f4lo(w2[k]), f4lo(hv), acc[s]);
                    fma2(acc[s], f4hi(w2[k]), f4hi(hv), acc[s]);
                }
            }
            float tot[S_PER_BLK];
            #pragma unroll
            for (int s = 0; s < S_PER_BLK; s++) {
                tot[s] = fold2(acc[s]);
                tot[s] += __shfl_xor_sync(0xffffffffu, tot[s], 1);
            }
            #pragma unroll
            for (int u = 0; u < 2; u++) {
                int s = (u == 0) ? sA : sB;
                float pre = tot[s] + bias1;
                ga1[s * G_DIM + g] = is_tanh ? ftanh(pre) : fsig(pre);
            }
        }
        __syncthreads();  // B3

        // ---------- layer 1 state update ----------
        if (tid < S_PER_BLK * H_DIM) {
            int s = tid >> 6, hh = tid & 63;
            float iv = ga1[s * G_DIM + hh];
            float fv = ga1[s * G_DIM + hh + H_DIM];
            float gv = ga1[s * G_DIM + hh + 2 * H_DIM];
            float ov = ga1[s * G_DIM + hh + 3 * H_DIM];
            float c  = __fmaf_rn(fv, c2s[tid], iv * gv);
            c2s[tid] = c;
            h2s[tid] = ov * ftanh(c);
        }
        // next-iter B1 orders h2s before its next read
    }
    __syncthreads();

    // ---------- classifier ----------
    if (tid < S_PER_BLK * 32) {
        int s = tid >> 5, j = tid & 31;
        float a = b_fc1[j];
        #pragma unroll
        for (int k = 0; k < H_DIM; k++)
            a = __fmaf_rn(h2s[s * H_DIM + k], W_fc1[j * H_DIM + k], a);
        ga0[s * 32 + j] = fmaxf(a, 0.f);
    }
    __syncthreads();
    if (tid < S_PER_BLK) {
        float a = b_fc2[0];
        #pragma unroll
        for (int j = 0; j < 32; j++)
            a = __fmaf_rn(ga0[tid * 32 + j], W_fc2[j], a);
        out[bb + tid] = fsig(a);
    }
}

extern "C" void kernel_launch(void* const* d_in, const int* in_sizes, int n_in,
                              void* d_out, int out_size)
{
    const float* x     = (const float*)d_in[0];
    const float* W_ih0 = (const float*)d_in[1];
    const float* W_hh0 = (const float*)d_in[2];
    const float* b0    = (const float*)d_in[3];
    const float* W_ih1 = (const float*)d_in[4];
    const float* W_hh1 = (const float*)d_in[5];
    const float* b1    = (const float*)d_in[6];
    const float* W_fc1 = (const float*)d_in[7];
    const float* b_fc1 = (const float*)d_in[8];
    const float* W_fc2 = (const float*)d_in[9];
    const float* b_fc2 = (const float*)d_in[10];
    float* out = (float*)d_out;

    const size_t smem_bytes =
        (size_t)(S_PER_BLK * T_STEPS * D_DIM
                 + 2 * S_PER_BLK * H_DIM           // h1s, h2s
                 + 2 * S_PER_BLK * G_DIM           // ga0, ga1
                 + 2 * S_PER_BLK * H_DIM)          // c1s, c2s
        * sizeof(float);

    cudaFuncSetAttribute(lstm_fused_kernel,
                         cudaFuncAttributeMaxDynamicSharedMemorySize,
                         (int)smem_bytes);

    const int nblocks = 512 / S_PER_BLK;   // 128
    lstm_fused_kernel<<<nblocks, NTHREADS, smem_bytes>>>(
        x, W_ih0, W_hh0, b0, W_ih1, W_hh1, b1,
        W_fc1, b_fc1, W_fc2, b_fc2, out);
}

// round 3
// speedup vs baseline: 1.4418x; 1.4418x over previous
#include <cuda_runtime.h>

#define S_PER_BLK 4
#define T_STEPS   1024
#define H_DIM     64
#define G_DIM     256   // 4*H
#define D_DIM     4
#define NTHREADS  256
#define W0_STRIDE 68    // padded row stride (floats) for W_hh0 in smem: conflict-free

typedef unsigned long long ull;

// ---- fast activations ----
__device__ __forceinline__ float fsig(float x) {
    float e = __expf(-x);
    float d = 1.0f + e;
    float r;
    asm("rcp.approx.f32 %0, %1;" : "=f"(r) : "f"(d));
    return r;
}
__device__ __forceinline__ float ftanh(float x) {
    return __fmaf_rn(2.0f, fsig(2.0f * x), -1.0f);
}

// ---- packed f32x2 fma (sm_100+) ----
__device__ __forceinline__ void fma2(ull& d, ull a, ull b, ull c) {
    asm("fma.rn.f32x2 %0, %1, %2, %3;" : "=l"(d) : "l"(a), "l"(b), "l"(c));
}
__device__ __forceinline__ float fold2(ull a) {
    float lo, hi;
    asm("mov.b64 {%0,%1}, %2;" : "=f"(lo), "=f"(hi) : "l"(a));
    return lo + hi;
}
__device__ __forceinline__ ull f4lo(const float4& v) {
    ull r; asm("mov.b64 %0, {%1,%2};" : "=l"(r) : "f"(v.x), "f"(v.y)); return r;
}
__device__ __forceinline__ ull f4hi(const float4& v) {
    ull r; asm("mov.b64 %0, {%1,%2};" : "=l"(r) : "f"(v.z), "f"(v.w)); return r;
}

// Dynamic smem layout (floats):
//   xs  : S*T*D        = 16384
//   w0s : G*W0_STRIDE  = 17408   (W_hh0, padded rows)
//   h1s : S*H          = 256
//   h2s : S*H          = 256
//   ga0 : S*G          = 1024
//   ga1 : S*G          = 1024
// total = 36352 floats = 145408 bytes

__global__ __launch_bounds__(NTHREADS, 1)
void lstm_fused_kernel(const float* __restrict__ x,
                       const float* __restrict__ W_ih0,
                       const float* __restrict__ W_hh0,
                       const float* __restrict__ b0,
                       const float* __restrict__ W_ih1,
                       const float* __restrict__ W_hh1,
                       const float* __restrict__ b1,
                       const float* __restrict__ W_fc1,
                       const float* __restrict__ b_fc1,
                       const float* __restrict__ W_fc2,
                       const float* __restrict__ b_fc2,
                       float* __restrict__ out)
{
    extern __shared__ float sm[];
    float* xs  = sm;                                    // [S][T][D]
    float* w0s = sm + S_PER_BLK * T_STEPS * D_DIM;      // [G][W0_STRIDE]
    float* h1s = w0s + G_DIM * W0_STRIDE;               // [S][H]
    float* h2s = h1s + S_PER_BLK * H_DIM;               // [S][H]
    float* ga0 = h2s + S_PER_BLK * H_DIM;               // [S][G]
    float* ga1 = ga0 + S_PER_BLK * G_DIM;               // [S][G]

    const int g  = threadIdx.x;      // gate row 0..255
    const int bb = blockIdx.x * S_PER_BLK;

    // ---- W_ih1 and W_hh1 rows in registers (128 regs) ----
    float4 w1[16], w2[16];
    {
        const float4* p1 = (const float4*)(W_ih1 + g * H_DIM);
        const float4* p2 = (const float4*)(W_hh1 + g * H_DIM);
        #pragma unroll
        for (int i = 0; i < 16; i++) { w1[i] = p1[i]; w2[i] = p2[i]; }
    }
    float wi0[D_DIM];
    #pragma unroll
    for (int d = 0; d < D_DIM; d++) wi0[d] = W_ih0[g * D_DIM + d];
    const float bias0 = b0[g];
    const float bias1 = b1[g];

    // ---- stage W_hh0 into padded smem (coalesced global reads) ----
    for (int i = g; i < G_DIM * H_DIM; i += NTHREADS) {
        int row = i >> 6, col = i & 63;
        w0s[row * W0_STRIDE + col] = W_hh0[i];
    }

    // ---- stage x into smem ----
    {
        const float4* gx = (const float4*)(x + (size_t)bb * T_STEPS * D_DIM);
        float4*       sx = (float4*)xs;
        #pragma unroll 4
        for (int i = g; i < S_PER_BLK * T_STEPS; i += NTHREADS) sx[i] = gx[i];
    }
    for (int i = g; i < S_PER_BLK * H_DIM; i += NTHREADS) { h1s[i] = 0.f; h2s[i] = 0.f; }

    // ---- per-thread cell state: thread tid owns (s = tid>>6, h = tid&63) ----
    float c1r = 0.f, c2r = 0.f;
    const int us = g >> 6;       // update sample
    const int uh = g & 63;       // update hidden index

    __syncthreads();

    const bool is_tanh = (g >= 2 * H_DIM) && (g < 3 * H_DIM);
    const float4* w0row = (const float4*)(w0s + g * W0_STRIDE);

    for (int t = 0; t < T_STEPS; t++) {
        // ---------- phase A: layer-0 gates. pre = b0 + x_t·Wih0 + h1·Whh0(smem) ----------
        {
            ull acc[S_PER_BLK];
            #pragma unroll
            for (int s = 0; s < S_PER_BLK; s++) acc[s] = 0ULL;
            #pragma unroll
            for (int k = 0; k < 16; k++) {
                const float4 wv = w0row[k];
                #pragma unroll
                for (int s = 0; s < S_PER_BLK; s++) {
                    const float4 hv = ((const float4*)(h1s + s * H_DIM))[k];
                    fma2(acc[s], f4lo(wv), f4lo(hv), acc[s]);
                    fma2(acc[s], f4hi(wv), f4hi(hv), acc[s]);
                }
            }
            #pragma unroll
            for (int s = 0; s < S_PER_BLK; s++) {
                const float4 xv = ((const float4*)xs)[s * T_STEPS + t];
                float pre = fold2(acc[s]) + bias0;
                pre = __fmaf_rn(xv.x, wi0[0], pre);
                pre = __fmaf_rn(xv.y, wi0[1], pre);
                pre = __fmaf_rn(xv.z, wi0[2], pre);
                pre = __fmaf_rn(xv.w, wi0[3], pre);
                ga0[s * G_DIM + g] = is_tanh ? ftanh(pre) : fsig(pre);
            }
        }
        __syncthreads();  // B1: ga0 ready

        // ---------- layer-0 state update: all 256 threads, one (s,h) each ----------
        {
            const float iv = ga0[us * G_DIM + uh];
            const float fv = ga0[us * G_DIM + uh + H_DIM];
            const float gv = ga0[us * G_DIM + uh + 2 * H_DIM];
            const float ov = ga0[us * G_DIM + uh + 3 * H_DIM];
            c1r = __fmaf_rn(fv, c1r, iv * gv);
            h1s[us * H_DIM + uh] = ov * ftanh(c1r);
        }
        __syncthreads();  // B2: h1s ready

        // ---------- phase C: layer-1 gates. pre = b1 + h1·Wih1 + h2·Whh1 (regs) ----------
        {
            ull acc[S_PER_BLK];
            #pragma unroll
            for (int s = 0; s < S_PER_BLK; s++) acc[s] = 0ULL;
            #pragma unroll
            for (int k = 0; k < 16; k++) {
                #pragma unroll
                for (int s = 0; s < S_PER_BLK; s++) {
                    const float4 hv = ((const float4*)(h1s + s * H_DIM))[k];
                    fma2(acc[s], f4lo(w1[k]), f4lo(hv), acc[s]);
                    fma2(acc[s], f4hi(w1[k]), f4hi(hv), acc[s]);
                }
            }
            #pragma unroll
            for (int k = 0; k < 16; k++) {
                #pragma unroll
                for (int s = 0; s < S_PER_BLK; s++) {
                    const float4 hv = ((const float4*)(h2s + s * H_DIM))[k];
                    fma2(acc[s], f4lo(w2[k]), f4lo(hv), acc[s]);
                    fma2(acc[s], f4hi(w2[k]), f4hi(hv), acc[s]);
                }
            }
            #pragma unroll
            for (int s = 0; s < S_PER_BLK; s++) {
                float pre = fold2(acc[s]) + bias1;
                ga1[s * G_DIM + g] = is_tanh ? ftanh(pre) : fsig(pre);
            }
        }
        __syncthreads();  // B3: ga1 ready (also orders h2s reads above vs write below)

        // ---------- layer-1 state update ----------
        {
            const float iv = ga1[us * G_DIM + uh];
            const float fv = ga1[us * G_DIM + uh + H_DIM];
            const float gv = ga1[us * G_DIM + uh + 2 * H_DIM];
            const float ov = ga1[us * G_DIM + uh + 3 * H_DIM];
            c2r = __fmaf_rn(fv, c2r, iv * gv);
            h2s[us * H_DIM + uh] = ov * ftanh(c2r);
        }
        // h2s next read is in phase C (t+1), ordered by next-iter B1+B2
        // h1s next write is update1 (t+1), after B1; its next read is phase A (t+1),
        // which precedes B1 — ordered because phase A reads h1s written before B2 of t. OK.
    }
    __syncthreads();

    // ---------- classifier ----------
    if (g < S_PER_BLK * 32) {
        int s = g >> 5, j = g & 31;
        float a = b_fc1[j];
        #pragma unroll
        for (int k = 0; k < H_DIM; k++)
            a = __fmaf_rn(h2s[s * H_DIM + k], W_fc1[j * H_DIM + k], a);
        ga0[s * 32 + j] = fmaxf(a, 0.f);
    }
    __syncthreads();
    if (g < S_PER_BLK) {
        float a = b_fc2[0];
        #pragma unroll
        for (int j = 0; j < 32; j++)
            a = __fmaf_rn(ga0[g * 32 + j], W_fc2[j], a);
        out[bb + g] = fsig(a);
    }
}

extern "C" void kernel_launch(void* const* d_in, const int* in_sizes, int n_in,
                              void* d_out, int out_size)
{
    const float* x     = (const float*)d_in[0];
    const float* W_ih0 = (const float*)d_in[1];
    const float* W_hh0 = (const float*)d_in[2];
    const float* b0    = (const float*)d_in[3];
    const float* W_ih1 = (const float*)d_in[4];
    const float* W_hh1 = (const float*)d_in[5];
    const float* b1    = (const float*)d_in[6];
    const float* W_fc1 = (const float*)d_in[7];
    const float* b_fc1 = (const float*)d_in[8];
    const float* W_fc2 = (const float*)d_in[9];
    const float* b_fc2 = (const float*)d_in[10];
    float* out = (float*)d_out;

    const size_t smem_bytes =
        (size_t)(S_PER_BLK * T_STEPS * D_DIM      // xs
                 + G_DIM * W0_STRIDE              // w0s
                 + 2 * S_PER_BLK * H_DIM          // h1s, h2s
                 + 2 * S_PER_BLK * G_DIM)         // ga0, ga1
        * sizeof(float);

    cudaFuncSetAttribute(lstm_fused_kernel,
                         cudaFuncAttributeMaxDynamicSharedMemorySize,
                         (int)smem_bytes);

    const int nblocks = 512 / S_PER_BLK;   // 128
    lstm_fused_kernel<<<nblocks, NTHREADS, smem_bytes>>>(
        x, W_ih0, W_hh0, b0, W_ih1, W_hh1, b1,
        W_fc1, b_fc1, W_fc2, b_fc2, out);
}

// round 4
// speedup vs baseline: 1.8777x; 1.3023x over previous
#include <cuda_runtime.h>

#define S_PER_BLK 4
#define T_STEPS   1024
#define H_DIM     64
#define G_DIM     256   // 4*H
#define D_DIM     4
#define NTHREADS  512   // 256 L0 threads + 256 L1 threads
#define W2_STRIDE 68    // W_hh1 smem row stride (floats): 272B -> conflict-free LDS.128

// named barrier ids
#define BAR_L0INT 1
#define BAR_L1INT 2
#define BAR_READY0 3
#define BAR_READY1 4
#define BAR_FREE0  5
#define BAR_FREE1  6

typedef unsigned long long ull;

__device__ __forceinline__ void bar_sync(int id, int cnt) {
    asm volatile("bar.sync %0, %1;" :: "r"(id), "r"(cnt) : "memory");
}
__device__ __forceinline__ void bar_arrive(int id, int cnt) {
    asm volatile("bar.arrive %0, %1;" :: "r"(id), "r"(cnt) : "memory");
}

// ---- fast activations ----
__device__ __forceinline__ float fsig(float x) {
    float e = __expf(-x);
    float d = 1.0f + e;
    float r;
    asm("rcp.approx.f32 %0, %1;" : "=f"(r) : "f"(d));
    return r;
}
__device__ __forceinline__ float ftanh(float x) {
    return __fmaf_rn(2.0f, fsig(2.0f * x), -1.0f);
}

// ---- packed f32x2 fma (sm_100+) ----
__device__ __forceinline__ void fma2(ull& d, ull a, ull b, ull c) {
    asm("fma.rn.f32x2 %0, %1, %2, %3;" : "=l"(d) : "l"(a), "l"(b), "l"(c));
}
__device__ __forceinline__ float fold2(ull a) {
    float lo, hi;
    asm("mov.b64 {%0,%1}, %2;" : "=f"(lo), "=f"(hi) : "l"(a));
    return lo + hi;
}
__device__ __forceinline__ ull f4lo(const float4& v) {
    ull r; asm("mov.b64 %0, {%1,%2};" : "=l"(r) : "f"(v.x), "f"(v.y)); return r;
}
__device__ __forceinline__ ull f4hi(const float4& v) {
    ull r; asm("mov.b64 %0, {%1,%2};" : "=l"(r) : "f"(v.z), "f"(v.w)); return r;
}

// smem layout (floats):
//   xs   : S*T*D        = 16384
//   w2s  : G*W2_STRIDE  = 17408   (W_hh1 padded rows, for L1 pre-wait partial)
//   ring : 2*S*H        = 512     (h1 double buffer, L0 -> L1)
//   h2s  : S*H          = 256
//   ga0  : S*G          = 1024
//   ga1  : S*G          = 1024
// total 36608 floats = 146432 bytes

__global__ __launch_bounds__(NTHREADS, 1)
void lstm_fused_kernel(const float* __restrict__ x,
                       const float* __restrict__ W_ih0,
                       const float* __restrict__ W_hh0,
                       const float* __restrict__ b0,
                       const float* __restrict__ W_ih1,
                       const float* __restrict__ W_hh1,
                       const float* __restrict__ b1,
                       const float* __restrict__ W_fc1,
                       const float* __restrict__ b_fc1,
                       const float* __restrict__ W_fc2,
                       const float* __restrict__ b_fc2,
                       float* __restrict__ out)
{
    extern __shared__ float sm[];
    float* xs   = sm;                                   // [S][T][D]
    float* w2s  = sm + S_PER_BLK * T_STEPS * D_DIM;     // [G][W2_STRIDE]
    float* ring = w2s + G_DIM * W2_STRIDE;              // [2][S][H]
    float* h2s  = ring + 2 * S_PER_BLK * H_DIM;         // [S][H]
    float* ga0  = h2s + S_PER_BLK * H_DIM;              // [S][G]
    float* ga1  = ga0 + S_PER_BLK * G_DIM;              // [S][G]

    const int tid  = threadIdx.x;
    const bool isL0 = tid < 256;
    const int g    = tid & 255;          // gate row within group
    const int bb   = blockIdx.x * S_PER_BLK;
    const int us   = g >> 6;             // update sample
    const int uh   = g & 63;             // update hidden idx
    const bool is_tanh = (g >= 2 * H_DIM) && (g < 3 * H_DIM);

    // ---- common staging ----
    // x
    {
        const float4* gx = (const float4*)(x + (size_t)bb * T_STEPS * D_DIM);
        float4*       sx = (float4*)xs;
        #pragma unroll 4
        for (int i = tid; i < S_PER_BLK * T_STEPS; i += NTHREADS) sx[i] = gx[i];
    }
    // W_hh1 -> padded smem
    for (int i = tid; i < G_DIM * H_DIM; i += NTHREADS) {
        int row = i >> 6, col = i & 63;
        w2s[row * W2_STRIDE + col] = W_hh1[i];
    }
    // zero state
    for (int i = tid; i < 2 * S_PER_BLK * H_DIM; i += NTHREADS) ring[i] = 0.f;
    for (int i = tid; i < S_PER_BLK * H_DIM; i += NTHREADS) h2s[i] = 0.f;

    __syncthreads();

    if (isL0) {
        // =========================== L0 group ===========================
        float4 w0[16];
        {
            const float4* p0 = (const float4*)(W_hh0 + g * H_DIM);
            #pragma unroll
            for (int i = 0; i < 16; i++) w0[i] = p0[i];
        }
        float wi0[D_DIM];
        #pragma unroll
        for (int d = 0; d < D_DIM; d++) wi0[d] = W_ih0[g * D_DIM + d];
        const float bias0 = b0[g];
        float c1r = 0.f;

        for (int t = 0; t < T_STEPS; t++) {
            const int p = t & 1;
            if (t >= 2) bar_sync(p ? BAR_FREE1 : BAR_FREE0, 512);  // slot p reusable

            // gates0: pre = b0 + x_t*Wih0 + h1(t-1)*Whh0
            const float4* h1p = (const float4*)(ring + (p ^ 1) * S_PER_BLK * H_DIM);
            ull acc[S_PER_BLK];
            #pragma unroll
            for (int s = 0; s < S_PER_BLK; s++) acc[s] = 0ULL;
            #pragma unroll
            for (int k = 0; k < 16; k++) {
                #pragma unroll
                for (int s = 0; s < S_PER_BLK; s++) {
                    const float4 hv = h1p[s * 16 + k];
                    fma2(acc[s], f4lo(w0[k]), f4lo(hv), acc[s]);
                    fma2(acc[s], f4hi(w0[k]), f4hi(hv), acc[s]);
                }
            }
            #pragma unroll
            for (int s = 0; s < S_PER_BLK; s++) {
                const float4 xv = ((const float4*)xs)[s * T_STEPS + t];
                float pre = fold2(acc[s]) + bias0;
                pre = __fmaf_rn(xv.x, wi0[0], pre);
                pre = __fmaf_rn(xv.y, wi0[1], pre);
                pre = __fmaf_rn(xv.z, wi0[2], pre);
                pre = __fmaf_rn(xv.w, wi0[3], pre);
                ga0[s * G_DIM + g] = is_tanh ? ftanh(pre) : fsig(pre);
            }
            bar_sync(BAR_L0INT, 256);                       // ga0 ready

            // state update -> h1(t) into ring[p]
            {
                const float iv = ga0[us * G_DIM + uh];
                const float fv = ga0[us * G_DIM + uh + H_DIM];
                const float gv = ga0[us * G_DIM + uh + 2 * H_DIM];
                const float ov = ga0[us * G_DIM + uh + 3 * H_DIM];
                c1r = __fmaf_rn(fv, c1r, iv * gv);
                ring[p * S_PER_BLK * H_DIM + us * H_DIM + uh] = ov * ftanh(c1r);
            }
            bar_sync(BAR_L0INT, 256);                       // ring[p] complete (for own t+1 read)
            bar_arrive(p ? BAR_READY1 : BAR_READY0, 512);   // publish h1(t) to L1
        }
    } else {
        // =========================== L1 group ===========================
        float4 w1[16];   // W_ih1 row (critical post-wait matvec) in regs
        {
            const float4* p1 = (const float4*)(W_ih1 + g * H_DIM);
            #pragma unroll
            for (int i = 0; i < 16; i++) w1[i] = p1[i];
        }
        const float bias1 = b1[g];
        float c2r = 0.f;
        const float4* w2row = (const float4*)(w2s + g * W2_STRIDE);

        ull acc[S_PER_BLK];          // carries h2*Whh1 partial across iterations
        #pragma unroll
        for (int s = 0; s < S_PER_BLK; s++) acc[s] = 0ULL;   // h2(−1)=0 -> zero partial

        for (int t = 0; t < T_STEPS; t++) {
            const int p = t & 1;

            bar_sync(p ? BAR_READY1 : BAR_READY0, 512);     // h1(t) ready

            // add h1(t)*Wih1 (register weights) to carried partial
            const float4* h1c = (const float4*)(ring + p * S_PER_BLK * H_DIM);
            #pragma unroll
            for (int k = 0; k < 16; k++) {
                #pragma unroll
                for (int s = 0; s < S_PER_BLK; s++) {
                    const float4 hv = h1c[s * 16 + k];
                    fma2(acc[s], f4lo(w1[k]), f4lo(hv), acc[s]);
                    fma2(acc[s], f4hi(w1[k]), f4hi(hv), acc[s]);
                }
            }
            bar_arrive(p ? BAR_FREE1 : BAR_FREE0, 512);     // done reading ring[p]

            #pragma unroll
            for (int s = 0; s < S_PER_BLK; s++) {
                float pre = fold2(acc[s]) + bias1;
                ga1[s * G_DIM + g] = is_tanh ? ftanh(pre) : fsig(pre);
            }
            bar_sync(BAR_L1INT, 256);                       // ga1 ready

            // layer-1 state update
            {
                const float iv = ga1[us * G_DIM + uh];
                const float fv = ga1[us * G_DIM + uh + H_DIM];
                const float gv = ga1[us * G_DIM + uh + 2 * H_DIM];
                const float ov = ga1[us * G_DIM + uh + 3 * H_DIM];
                c2r = __fmaf_rn(fv, c2r, iv * gv);
                h2s[us * H_DIM + uh] = ov * ftanh(c2r);
            }
            bar_sync(BAR_L1INT, 256);                       // h2(t) visible to all L1

            // precompute next step's h2*Whh1 partial (overlaps next ready-wait)
            #pragma unroll
            for (int s = 0; s < S_PER_BLK; s++) acc[s] = 0ULL;
            #pragma unroll
            for (int k = 0; k < 16; k++) {
                const float4 wv = w2row[k];
                #pragma unroll
                for (int s = 0; s < S_PER_BLK; s++) {
                    const float4 hv = ((const float4*)h2s)[s * 16 + k];
                    fma2(acc[s], f4lo(wv), f4lo(hv), acc[s]);
                    fma2(acc[s], f4hi(wv), f4hi(hv), acc[s]);
                }
            }
        }
    }

    __syncthreads();

    // ---------- classifier ----------
    if (tid < S_PER_BLK * 32) {
        int s = tid >> 5, j = tid & 31;
        float a = b_fc1[j];
        #pragma unroll
        for (int k = 0; k < H_DIM; k++)
            a = __fmaf_rn(h2s[s * H_DIM + k], W_fc1[j * H_DIM + k], a);
        ga0[s * 32 + j] = fmaxf(a, 0.f);
    }
    __syncthreads();
    if (tid < S_PER_BLK) {
        float a = b_fc2[0];
        #pragma unroll
        for (int j = 0; j < 32; j++)
            a = __fmaf_rn(ga0[tid * 32 + j], W_fc2[j], a);
        out[bb + tid] = fsig(a);
    }
}

extern "C" void kernel_launch(void* const* d_in, const int* in_sizes, int n_in,
                              void* d_out, int out_size)
{
    const float* x     = (const float*)d_in[0];
    const float* W_ih0 = (const float*)d_in[1];
    const float* W_hh0 = (const float*)d_in[2];
    const float* b0    = (const float*)d_in[3];
    const float* W_ih1 = (const float*)d_in[4];
    const float* W_hh1 = (const float*)d_in[5];
    const float* b1    = (const float*)d_in[6];
    const float* W_fc1 = (const float*)d_in[7];
    const float* b_fc1 = (const float*)d_in[8];
    const float* W_fc2 = (const float*)d_in[9];
    const float* b_fc2 = (const float*)d_in[10];
    float* out = (float*)d_out;

    const size_t smem_bytes =
        (size_t)(S_PER_BLK * T_STEPS * D_DIM      // xs
                 + G_DIM * W2_STRIDE              // w2s
                 + 2 * S_PER_BLK * H_DIM          // ring
                 + S_PER_BLK * H_DIM              // h2s
                 + 2 * S_PER_BLK * G_DIM)         // ga0, ga1
        * sizeof(float);

    cudaFuncSetAttribute(lstm_fused_kernel,
                         cudaFuncAttributeMaxDynamicSharedMemorySize,
                         (int)smem_bytes);

    const int nblocks = 512 / S_PER_BLK;   // 128
    lstm_fused_kernel<<<nblocks, NTHREADS, smem_bytes>>>(
        x, W_ih0, W_hh0, b0, W_ih1, W_hh1, b1,
        W_fc1, b_fc1, W_fc2, b_fc2, out);
}

// round 5
// speedup vs baseline: 1.9138x; 1.0192x over previous
#include <cuda_runtime.h>

#define S_PER_BLK 4
#define T_STEPS   1024
#define H_DIM     64
#define G_DIM     256   // 4*H
#define D_DIM     4
#define NTHREADS  384   // 128 L0 threads (2 rows each) + 256 L1 threads (1 row)
#define L0_SZ     128
#define L1_SZ     256

// named barrier ids
#define BAR_L0INT  1
#define BAR_L1INT  2
#define BAR_READY0 3
#define BAR_READY1 4
#define BAR_FREE0  5
#define BAR_FREE1  6

typedef unsigned long long ull;

__device__ __forceinline__ void bar_sync(int id, int cnt) {
    asm volatile("bar.sync %0, %1;" :: "r"(id), "r"(cnt) : "memory");
}
__device__ __forceinline__ void bar_arrive(int id, int cnt) {
    asm volatile("bar.arrive %0, %1;" :: "r"(id), "r"(cnt) : "memory");
}

// ---- fast activations ----
__device__ __forceinline__ float fsig(float x) {
    float e = __expf(-x);
    float d = 1.0f + e;
    float r;
    asm("rcp.approx.f32 %0, %1;" : "=f"(r) : "f"(d));
    return r;
}
__device__ __forceinline__ float ftanh(float x) {
    return __fmaf_rn(2.0f, fsig(2.0f * x), -1.0f);
}

// ---- packed f32x2 fma (sm_100+) ----
__device__ __forceinline__ void fma2(ull& d, ull a, ull b, ull c) {
    asm("fma.rn.f32x2 %0, %1, %2, %3;" : "=l"(d) : "l"(a), "l"(b), "l"(c));
}
__device__ __forceinline__ float fold2(ull a) {
    float lo, hi;
    asm("mov.b64 {%0,%1}, %2;" : "=f"(lo), "=f"(hi) : "l"(a));
    return lo + hi;
}
__device__ __forceinline__ ull f4lo(const float4& v) {
    ull r; asm("mov.b64 %0, {%1,%2};" : "=l"(r) : "f"(v.x), "f"(v.y)); return r;
}
__device__ __forceinline__ ull f4hi(const float4& v) {
    ull r; asm("mov.b64 %0, {%1,%2};" : "=l"(r) : "f"(v.z), "f"(v.w)); return r;
}

// smem layout (floats):
//   xs   : S*T*D = 16384
//   ring : 2*S*H = 512     (h1 double buffer, L0 -> L1)
//   h2s  : S*H   = 256
//   ga0  : S*G   = 1024
//   ga1  : S*G   = 1024
// total 19200 floats = 76800 bytes

__global__ __launch_bounds__(NTHREADS, 1)
void lstm_fused_kernel(const float* __restrict__ x,
                       const float* __restrict__ W_ih0,
                       const float* __restrict__ W_hh0,
                       const float* __restrict__ b0,
                       const float* __restrict__ W_ih1,
                       const float* __restrict__ W_hh1,
                       const float* __restrict__ b1,
                       const float* __restrict__ W_fc1,
                       const float* __restrict__ b_fc1,
                       const float* __restrict__ W_fc2,
                       const float* __restrict__ b_fc2,
                       float* __restrict__ out)
{
    extern __shared__ float sm[];
    float* xs   = sm;                                   // [S][T][D]
    float* ring = sm + S_PER_BLK * T_STEPS * D_DIM;     // [2][S][H]
    float* h2s  = ring + 2 * S_PER_BLK * H_DIM;         // [S][H]
    float* ga0  = h2s + S_PER_BLK * H_DIM;              // [S][G]
    float* ga1  = ga0 + S_PER_BLK * G_DIM;              // [S][G]

    const int tid  = threadIdx.x;
    const bool isL0 = tid < L0_SZ;
    const int bb   = blockIdx.x * S_PER_BLK;

    // ---- common staging ----
    {
        const float4* gx = (const float4*)(x + (size_t)bb * T_STEPS * D_DIM);
        float4*       sx = (float4*)xs;
        #pragma unroll 4
        for (int i = tid; i < S_PER_BLK * T_STEPS; i += NTHREADS) sx[i] = gx[i];
    }
    for (int i = tid; i < 2 * S_PER_BLK * H_DIM; i += NTHREADS) ring[i] = 0.f;
    for (int i = tid; i < S_PER_BLK * H_DIM; i += NTHREADS) h2s[i] = 0.f;

    __syncthreads();

    if (isL0) {
        // ================= L0 group: 128 threads, rows g and g+128 =================
        const int gA = tid;          // row in [0,128): i or f gate -> sigmoid
        const int gB = tid + 128;    // row in [128,256): tanh if tid<64 else sigmoid
        const bool tanhB = (tid < 64);

        float4 w0a[16], w0b[16];
        {
            const float4* pa = (const float4*)(W_hh0 + gA * H_DIM);
            const float4* pb = (const float4*)(W_hh0 + gB * H_DIM);
            #pragma unroll
            for (int i = 0; i < 16; i++) { w0a[i] = pa[i]; w0b[i] = pb[i]; }
        }
        float wiA[D_DIM], wiB[D_DIM];
        #pragma unroll
        for (int d = 0; d < D_DIM; d++) {
            wiA[d] = W_ih0[gA * D_DIM + d];
            wiB[d] = W_ih0[gB * D_DIM + d];
        }
        const float biasA = b0[gA];
        const float biasB = b0[gB];

        // update ownership: pairs 2*tid and 2*tid+1 of the 256 (s,h) pairs
        const int p0s = (2 * tid) >> 6, p0h = (2 * tid) & 63;
        const int p1s = (2 * tid + 1) >> 6, p1h = (2 * tid + 1) & 63;
        float c1r0 = 0.f, c1r1 = 0.f;

        for (int t = 0; t < T_STEPS; t++) {
            const int p = t & 1;
            if (t >= 2) bar_sync(p ? BAR_FREE1 : BAR_FREE0, NTHREADS);

            const float4* h1p = (const float4*)(ring + (p ^ 1) * S_PER_BLK * H_DIM);

            // two sample-half passes -> only 4 live accumulators
            #pragma unroll
            for (int half = 0; half < 2; half++) {
                const int s0 = 2 * half, s1 = s0 + 1;
                ull aA0 = 0, aA1 = 0, aB0 = 0, aB1 = 0;
                #pragma unroll
                for (int k = 0; k < 16; k++) {
                    const float4 hv0 = h1p[s0 * 16 + k];
                    const float4 hv1 = h1p[s1 * 16 + k];
                    fma2(aA0, f4lo(w0a[k]), f4lo(hv0), aA0);
                    fma2(aA0, f4hi(w0a[k]), f4hi(hv0), aA0);
                    fma2(aA1, f4lo(w0a[k]), f4lo(hv1), aA1);
                    fma2(aA1, f4hi(w0a[k]), f4hi(hv1), aA1);
                    fma2(aB0, f4lo(w0b[k]), f4lo(hv0), aB0);
                    fma2(aB0, f4hi(w0b[k]), f4hi(hv0), aB0);
                    fma2(aB1, f4lo(w0b[k]), f4lo(hv1), aB1);
                    fma2(aB1, f4hi(w0b[k]), f4hi(hv1), aB1);
                }
                const float4 xv0 = ((const float4*)xs)[s0 * T_STEPS + t];
                const float4 xv1 = ((const float4*)xs)[s1 * T_STEPS + t];

                float pA0 = fold2(aA0) + biasA;
                pA0 = __fmaf_rn(xv0.x, wiA[0], pA0);
                pA0 = __fmaf_rn(xv0.y, wiA[1], pA0);
                pA0 = __fmaf_rn(xv0.z, wiA[2], pA0);
                pA0 = __fmaf_rn(xv0.w, wiA[3], pA0);
                ga0[s0 * G_DIM + gA] = fsig(pA0);

                float pA1 = fold2(aA1) + biasA;
                pA1 = __fmaf_rn(xv1.x, wiA[0], pA1);
                pA1 = __fmaf_rn(xv1.y, wiA[1], pA1);
                pA1 = __fmaf_rn(xv1.z, wiA[2], pA1);
                pA1 = __fmaf_rn(xv1.w, wiA[3], pA1);
                ga0[s1 * G_DIM + gA] = fsig(pA1);

                float pB0 = fold2(aB0) + biasB;
                pB0 = __fmaf_rn(xv0.x, wiB[0], pB0);
                pB0 = __fmaf_rn(xv0.y, wiB[1], pB0);
                pB0 = __fmaf_rn(xv0.z, wiB[2], pB0);
                pB0 = __fmaf_rn(xv0.w, wiB[3], pB0);
                ga0[s0 * G_DIM + gB] = tanhB ? ftanh(pB0) : fsig(pB0);

                float pB1 = fold2(aB1) + biasB;
                pB1 = __fmaf_rn(xv1.x, wiB[0], pB1);
                pB1 = __fmaf_rn(xv1.y, wiB[1], pB1);
                pB1 = __fmaf_rn(xv1.z, wiB[2], pB1);
                pB1 = __fmaf_rn(xv1.w, wiB[3], pB1);
                ga0[s1 * G_DIM + gB] = tanhB ? ftanh(pB1) : fsig(pB1);
            }
            bar_sync(BAR_L0INT, L0_SZ);                     // ga0 ready

            // state update: 2 (s,h) pairs per thread -> ring[p]
            {
                float iv = ga0[p0s * G_DIM + p0h];
                float fv = ga0[p0s * G_DIM + p0h + H_DIM];
                float gv = ga0[p0s * G_DIM + p0h + 2 * H_DIM];
                float ov = ga0[p0s * G_DIM + p0h + 3 * H_DIM];
                c1r0 = __fmaf_rn(fv, c1r0, iv * gv);
                ring[p * S_PER_BLK * H_DIM + p0s * H_DIM + p0h] = ov * ftanh(c1r0);

                iv = ga0[p1s * G_DIM + p1h];
                fv = ga0[p1s * G_DIM + p1h + H_DIM];
                gv = ga0[p1s * G_DIM + p1h + 2 * H_DIM];
                ov = ga0[p1s * G_DIM + p1h + 3 * H_DIM];
                c1r1 = __fmaf_rn(fv, c1r1, iv * gv);
                ring[p * S_PER_BLK * H_DIM + p1s * H_DIM + p1h] = ov * ftanh(c1r1);
            }
            bar_sync(BAR_L0INT, L0_SZ);                     // ring[p] complete
            bar_arrive(p ? BAR_READY1 : BAR_READY0, NTHREADS);
        }
    } else {
        // ================= L1 group: 256 threads, 1 row, both matrices in regs =================
        const int g = tid - L0_SZ;
        const bool is_tanh = (g >= 2 * H_DIM) && (g < 3 * H_DIM);
        const int us = g >> 6, uh = g & 63;

        float4 w1[16], w2[16];
        {
            const float4* p1 = (const float4*)(W_ih1 + g * H_DIM);
            const float4* p2 = (const float4*)(W_hh1 + g * H_DIM);
            #pragma unroll
            for (int i = 0; i < 16; i++) { w1[i] = p1[i]; w2[i] = p2[i]; }
        }
        const float bias1 = b1[g];
        float c2r = 0.f;

        ull acc[S_PER_BLK];      // carried h2*Whh1 partial
        #pragma unroll
        for (int s = 0; s < S_PER_BLK; s++) acc[s] = 0ULL;

        for (int t = 0; t < T_STEPS; t++) {
            const int p = t & 1;

            bar_sync(p ? BAR_READY1 : BAR_READY0, NTHREADS);   // h1(t) ready

            const float4* h1c = (const float4*)(ring + p * S_PER_BLK * H_DIM);
            #pragma unroll
            for (int k = 0; k < 16; k++) {
                #pragma unroll
                for (int s = 0; s < S_PER_BLK; s++) {
                    const float4 hv = h1c[s * 16 + k];
                    fma2(acc[s], f4lo(w1[k]), f4lo(hv), acc[s]);
                    fma2(acc[s], f4hi(w1[k]), f4hi(hv), acc[s]);
                }
            }
            bar_arrive(p ? BAR_FREE1 : BAR_FREE0, NTHREADS);   // done with ring[p]

            #pragma unroll
            for (int s = 0; s < S_PER_BLK; s++) {
                float pre = fold2(acc[s]) + bias1;
                ga1[s * G_DIM + g] = is_tanh ? ftanh(pre) : fsig(pre);
            }
            bar_sync(BAR_L1INT, L1_SZ);                        // ga1 ready

            {
                const float iv = ga1[us * G_DIM + uh];
                const float fv = ga1[us * G_DIM + uh + H_DIM];
                const float gv = ga1[us * G_DIM + uh + 2 * H_DIM];
                const float ov = ga1[us * G_DIM + uh + 3 * H_DIM];
                c2r = __fmaf_rn(fv, c2r, iv * gv);
                h2s[us * H_DIM + uh] = ov * ftanh(c2r);
            }
            bar_sync(BAR_L1INT, L1_SZ);                        // h2(t) visible

            // precompute next step's h2*Whh1 partial (register weights)
            #pragma unroll
            for (int s = 0; s < S_PER_BLK; s++) acc[s] = 0ULL;
            #pragma unroll
            for (int k = 0; k < 16; k++) {
                #pragma unroll
                for (int s = 0; s < S_PER_BLK; s++) {
                    const float4 hv = ((const float4*)h2s)[s * 16 + k];
                    fma2(acc[s], f4lo(w2[k]), f4lo(hv), acc[s]);
                    fma2(acc[s], f4hi(w2[k]), f4hi(hv), acc[s]);
                }
            }
        }
    }

    __syncthreads();

    // ---------- classifier ----------
    if (tid < S_PER_BLK * 32) {
        int s = tid >> 5, j = tid & 31;
        float a = b_fc1[j];
        #pragma unroll
        for (int k = 0; k < H_DIM; k++)
            a = __fmaf_rn(h2s[s * H_DIM + k], W_fc1[j * H_DIM + k], a);
        ga0[s * 32 + j] = fmaxf(a, 0.f);
    }
    __syncthreads();
    if (tid < S_PER_BLK) {
        float a = b_fc2[0];
        #pragma unroll
        for (int j = 0; j < 32; j++)
            a = __fmaf_rn(ga0[tid * 32 + j], W_fc2[j], a);
        out[bb + tid] = fsig(a);
    }
}

extern "C" void kernel_launch(void* const* d_in, const int* in_sizes, int n_in,
                              void* d_out, int out_size)
{
    const float* x     = (const float*)d_in[0];
    const float* W_ih0 = (const float*)d_in[1];
    const float* W_hh0 = (const float*)d_in[2];
    const float* b0    = (const float*)d_in[3];
    const float* W_ih1 = (const float*)d_in[4];
    const float* W_hh1 = (const float*)d_in[5];
    const float* b1    = (const float*)d_in[6];
    const float* W_fc1 = (const float*)d_in[7];
    const float* b_fc1 = (const float*)d_in[8];
    const float* W_fc2 = (const float*)d_in[9];
    const float* b_fc2 = (const float*)d_in[10];
    float* out = (float*)d_out;

    const size_t smem_bytes =
        (size_t)(S_PER_BLK * T_STEPS * D_DIM      // xs
                 + 2 * S_PER_BLK * H_DIM          // ring
                 + S_PER_BLK * H_DIM              // h2s
                 + 2 * S_PER_BLK * G_DIM)         // ga0, ga1
        * sizeof(float);

    cudaFuncSetAttribute(lstm_fused_kernel,
                         cudaFuncAttributeMaxDynamicSharedMemorySize,
                         (int)smem_bytes);

    const int nblocks = 512 / S_PER_BLK;   // 128
    lstm_fused_kernel<<<nblocks, NTHREADS, smem_bytes>>>(
        x, W_ih0, W_hh0, b0, W_ih1, W_hh1, b1,
        W_fc1, b_fc1, W_fc2, b_fc2, out);
}